// round 15
// baseline (speedup 1.0000x reference)
#include <cuda_runtime.h>
#include <cuda_bf16.h>
#include <cstdint>
#include <math.h>

// Problem constants
#define BB 4
#define SS 2048
#define EE 2048
#define HH 16
#define DD 128
#define DH 64   // DD/2

#define MM (BB * SS)              // 8192
#define NELEM ((size_t)MM * EE)   // 16,777,216
#define WELEM ((size_t)EE * EE)   // 4,194,304

// ---------------------------------------------------------------------------
// Scratch (device globals — no allocation allowed in kernel_launch)
// ---------------------------------------------------------------------------
__device__ float g_q[NELEM];
__device__ float g_k[NELEM];
__device__ float g_v[NELEM];
__device__ float g_attn[NELEM];

__device__ char g_xq_h[NELEM],  g_xq_l[NELEM];
__device__ char g_xkv_h[NELEM], g_xkv_l[NELEM];
__device__ char g_at_h[NELEM],  g_at_l[NELEM];
__device__ char g_wq_h[WELEM], g_wq_l[WELEM];
__device__ char g_wk_h[WELEM], g_wk_l[WELEM];
__device__ char g_wv_h[WELEM], g_wv_l[WELEM];
__device__ char g_wo_h[WELEM], g_wo_l[WELEM];
__device__ float g_sxq[MM], g_sxkv[MM], g_sat[MM];
__device__ float g_swq[EE], g_swk[EE], g_swv[EE], g_swo[EE];

// attention operands
__device__ char g_q8h[NELEM], g_q8l[NELEM];
__device__ char g_k8h[NELEM], g_k8l[NELEM];
__device__ float g_sq8[(size_t)HH * MM], g_sk8[(size_t)HH * MM];  // [H][M]
__device__ char g_v8h[NELEM], g_v8l[NELEM];          // transposed tiles
__device__ float g_svt[(size_t)BB * HH * 32 * 128];  // per (b,h,tile,d)

// ---------------------------------------------------------------------------
// helpers
// ---------------------------------------------------------------------------
__device__ __forceinline__ uint32_t smem_u32(const void* p) {
    uint32_t a;
    asm("{ .reg .u64 t; cvta.to.shared.u64 t, %1; cvt.u32.u64 %0, t; }"
        : "=r"(a) : "l"(p));
    return a;
}

__device__ __forceinline__ void ldsm4(uint32_t* r, uint32_t addr) {
    asm volatile("ldmatrix.sync.aligned.m8n8.x4.shared.b16 {%0,%1,%2,%3}, [%4];"
        : "=r"(r[0]), "=r"(r[1]), "=r"(r[2]), "=r"(r[3]) : "r"(addr));
}

__device__ __forceinline__ void mma_s8(int* d, const uint32_t* a,
                                       const uint32_t* b) {
    asm volatile(
        "mma.sync.aligned.m16n8k32.row.col.s32.s8.s8.s32 "
        "{%0,%1,%2,%3}, {%4,%5,%6,%7}, {%8,%9}, {%0,%1,%2,%3};"
        : "+r"(d[0]), "+r"(d[1]), "+r"(d[2]), "+r"(d[3])
        : "r"(a[0]), "r"(a[1]), "r"(a[2]), "r"(a[3]), "r"(b[0]), "r"(b[1]));
}

__device__ __forceinline__ void cp16(uint32_t dst, const void* src) {
    asm volatile("cp.async.ca.shared.global [%0], [%1], 16;"
        :: "r"(dst), "l"((uint64_t)__cvta_generic_to_global(src)));
}
#define CP_COMMIT() asm volatile("cp.async.commit_group;")
#define CP_WAIT(n)  asm volatile("cp.async.wait_group %0;" :: "n"(n))

// ---------------------------------------------------------------------------
// Quantize rows: fp32 [rows, 2048] -> int8 h,l with per-row scale.
// w ~= s*(128*h + l), s = rowAbsMax/16256.
// ---------------------------------------------------------------------------
__global__ __launch_bounds__(256) void quant_rows_kernel(
    const float* __restrict__ src, char* __restrict__ h8,
    char* __restrict__ l8, float* __restrict__ scale)
{
    const int row = blockIdx.x;
    const int tid = threadIdx.x;
    const float* r = src + (size_t)row * 2048 + tid * 8;
    float4 v0 = *(const float4*)(r);
    float4 v1 = *(const float4*)(r + 4);
    float w[8] = {v0.x, v0.y, v0.z, v0.w, v1.x, v1.y, v1.z, v1.w};

    float m = 0.f;
#pragma unroll
    for (int e = 0; e < 8; e++) m = fmaxf(m, fabsf(w[e]));
#pragma unroll
    for (int o = 16; o > 0; o >>= 1)
        m = fmaxf(m, __shfl_xor_sync(0xffffffffu, m, o));

    __shared__ float red[8];
    __shared__ float ssc;
    if ((tid & 31) == 0) red[tid >> 5] = m;
    __syncthreads();
    if (tid == 0) {
        float mm = red[0];
#pragma unroll
        for (int i = 1; i < 8; i++) mm = fmaxf(mm, red[i]);
        float s = (mm > 0.f) ? mm / 16256.f : 1.f;
        ssc = s;
        scale[row] = s;
    }
    __syncthreads();
    const float inv = 1.f / ssc;

    char h[8], l[8];
#pragma unroll
    for (int e = 0; e < 8; e++) {
        float t = w[e] * inv;
        float hq = rintf(t * (1.f / 128.f));
        float lq = rintf(t - 128.f * hq);
        h[e] = (char)(int)hq;
        l[e] = (char)(int)lq;
    }
    size_t o8 = (size_t)row * 2048 + tid * 8;
    *(uint2*)(h8 + o8) = *(uint2*)h;
    *(uint2*)(l8 + o8) = *(uint2*)l;
}

// ---------------------------------------------------------------------------
// Fused RoPE + two-level int8 quant per (b,s,h) head-row. scale: [H][M].
// ---------------------------------------------------------------------------
__global__ __launch_bounds__(128) void rope_quant_kernel(
    const float* __restrict__ x, const float* __restrict__ angles,
    const int* __restrict__ flag, int always,
    char* __restrict__ h8, char* __restrict__ l8, float* __restrict__ scale)
{
    const int wid  = threadIdx.x >> 5;
    const int lane = threadIdx.x & 31;
    const int g = blockIdx.x * 4 + wid;          // over BB*SS*HH
    const int b    = g / (SS * HH);
    const int rem  = g % (SS * HH);
    const int spos = rem / HH;
    const int h    = rem % HH;
    const size_t base = (size_t)g * DD;
    const bool doRope = always || (*flag != 0);

    const int d0 = lane, d1 = lane + 32;
    float x1a = x[base + d0], x2a = x[base + d0 + DH];
    float x1b = x[base + d1], x2b = x[base + d1 + DH];
    float y[4];
    if (doRope) {
        float sn0 = angles[(size_t)spos * DH + d0];
        float cs0 = angles[(size_t)SS * DH + (size_t)spos * DH + d0];
        float sn1 = angles[(size_t)spos * DH + d1];
        float cs1 = angles[(size_t)SS * DH + (size_t)spos * DH + d1];
        y[0] = x1a * cs0 - x2a * sn0;
        y[1] = x1a * sn0 + x2a * cs0;
        y[2] = x1b * cs1 - x2b * sn1;
        y[3] = x1b * sn1 + x2b * cs1;
    } else {
        y[0] = x1a; y[1] = x2a; y[2] = x1b; y[3] = x2b;
    }

    float m = fmaxf(fmaxf(fabsf(y[0]), fabsf(y[1])),
                    fmaxf(fabsf(y[2]), fabsf(y[3])));
#pragma unroll
    for (int o = 16; o > 0; o >>= 1)
        m = fmaxf(m, __shfl_xor_sync(0xffffffffu, m, o));
    float s = (m > 0.f) ? m / 16256.f : 1.f;
    float inv = 1.f / s;

    char hq[4], lq[4];
#pragma unroll
    for (int e = 0; e < 4; e++) {
        float t = y[e] * inv;
        float hv = rintf(t * (1.f / 128.f));
        float lv = rintf(t - 128.f * hv);
        hq[e] = (char)(int)hv;
        lq[e] = (char)(int)lv;
    }
    h8[base + d0]      = hq[0];
    h8[base + d0 + DH] = hq[1];
    h8[base + d1]      = hq[2];
    h8[base + d1 + DH] = hq[3];
    l8[base + d0]      = lq[0];
    l8[base + d0 + DH] = lq[1];
    l8[base + d1]      = lq[2];
    l8[base + d1 + DH] = lq[3];
    if (lane == 0)
        scale[(size_t)h * MM + (size_t)b * SS + spos] = s;
}

// ---------------------------------------------------------------------------
// V quant: fp32 V [B,S,H*128] -> transposed int8 tiles.
// Block per (b,h,tile); thread d=0..127 reduces 64 tokens of column d.
// Output: v8[((b*HH+h)*32+tile)*8192 + d*64 + tok], scale per (g,d).
// ---------------------------------------------------------------------------
__global__ __launch_bounds__(128) void vquant_kernel(
    const float* __restrict__ v, char* __restrict__ v8h,
    char* __restrict__ v8l, float* __restrict__ svt)
{
    const int g = blockIdx.x;            // (b*HH+h)*32 + tile
    const int tile = g & 31;
    const int bh = g >> 5;
    const int b = bh >> 4, h = bh & 15;
    const int d = threadIdx.x;

    const float* src = v + ((size_t)b * SS + tile * 64) * 2048 + h * 128 + d;
    float vals[64];
    float m = 0.f;
#pragma unroll
    for (int t = 0; t < 64; t++) {
        vals[t] = src[(size_t)t * 2048];
        m = fmaxf(m, fabsf(vals[t]));
    }
    float s = (m > 0.f) ? m / 16256.f : 1.f;
    float inv = 1.f / s;

    char h8[64], l8[64];
#pragma unroll
    for (int t = 0; t < 64; t++) {
        float tt = vals[t] * inv;
        float hv = rintf(tt * (1.f / 128.f));
        float lv = rintf(tt - 128.f * hv);
        h8[t] = (char)(int)hv;
        l8[t] = (char)(int)lv;
    }
    size_t ob = (size_t)g * 8192 + (size_t)d * 64;
#pragma unroll
    for (int sg = 0; sg < 4; sg++) {
        *(uint4*)(v8h + ob + sg * 16) = *(uint4*)(h8 + sg * 16);
        *(uint4*)(v8l + ob + sg * 16) = *(uint4*)(l8 + sg * 16);
    }
    svt[(size_t)g * 128 + d] = s;
}

// ---------------------------------------------------------------------------
// int8 tensor-core GEMM (VALIDATED R11): C = A @ W^T + bias, two-level 3-term.
// ---------------------------------------------------------------------------
#define GBM 128
#define GBN 128
#define GBK 64
#define LDS 40
#define BUFB (GBM * LDS * 2)       // 10240
#define GEMM_SMEM_BYTES (BUFB * 8)

__global__ __launch_bounds__(512) void gemm_s8_kernel(
    const char* __restrict__ Ah, const char* __restrict__ Al,
    const char* __restrict__ Bh, const char* __restrict__ Bl,
    const float* __restrict__ sA, const float* __restrict__ sB,
    const float* __restrict__ bias, float* __restrict__ C,
    int M, int N, int K)
{
    extern __shared__ __align__(16) char dsmem[];
    const uint32_t sb = smem_u32(dsmem);

    const int tid  = threadIdx.x;
    const int lane = tid & 31;
    const int wid  = tid >> 5;
    const int wm   = wid & 7;
    const int wn   = wid >> 3;
    const size_t m0 = (size_t)blockIdx.y * GBM;
    const size_t n0 = (size_t)blockIdx.x * GBN;

    int acc_hh[8][4], acc_x[8][4];
#pragma unroll
    for (int j = 0; j < 8; j++)
#pragma unroll
        for (int e = 0; e < 4; e++) { acc_hh[j][e] = 0; acc_x[j][e] = 0; }

    const int ra = tid >> 2;
    const int ca = tid & 3;

    const int a_row = wm * 16 + (lane & 15);
    const int a_col = (lane >> 4) << 3;
    const int b_row = wn * 64 + ((lane >> 4) << 3) + (lane & 7);
    const int b_col = ((lane >> 3) & 1) << 3;

    const int nChunks = K / GBK;

#define PREFETCH8(c, s) do {                                                    \
    size_t ca64 = (size_t)(c) * GBK;                                            \
    uint32_t d = (uint32_t)(ra * 80 + ca * 16);                                 \
    cp16(sb + (0 + (s)) * BUFB + d, Ah + (m0 + ra) * (size_t)K + ca64 + ca * 16); \
    cp16(sb + (2 + (s)) * BUFB + d, Al + (m0 + ra) * (size_t)K + ca64 + ca * 16); \
    cp16(sb + (4 + (s)) * BUFB + d, Bh + (n0 + ra) * (size_t)K + ca64 + ca * 16); \
    cp16(sb + (6 + (s)) * BUFB + d, Bl + (n0 + ra) * (size_t)K + ca64 + ca * 16); \
} while (0)

    PREFETCH8(0, 0);
    CP_COMMIT();

    for (int c = 0; c < nChunks; c++) {
        const int s = c & 1;
        if (c + 1 < nChunks) {
            PREFETCH8(c + 1, s ^ 1);
            CP_COMMIT();
            CP_WAIT(1);
        } else {
            CP_WAIT(0);
        }
        __syncthreads();

        const uint32_t uAh = sb + (0 + s) * BUFB;
        const uint32_t uAl = sb + (2 + s) * BUFB;
        const uint32_t uBh = sb + (4 + s) * BUFB;
        const uint32_t uBl = sb + (6 + s) * BUFB;

#pragma unroll
        for (int ks = 0; ks < 2; ks++) {
            const int kk = ks * 16;
            uint32_t ah[4], al[4];
            uint32_t aoff = (uint32_t)((a_row * LDS + kk + a_col) * 2);
            ldsm4(ah, uAh + aoff);
            ldsm4(al, uAl + aoff);
#pragma unroll
            for (int nb = 0; nb < 4; nb++) {
                uint32_t boff = (uint32_t)(((b_row + nb * 16) * LDS + kk + b_col) * 2);
                uint32_t bh[4], bl[4];
                ldsm4(bh, uBh + boff);
                ldsm4(bl, uBl + boff);
                mma_s8(acc_hh[nb * 2 + 0], ah, bh + 0);
                mma_s8(acc_hh[nb * 2 + 1], ah, bh + 2);
                mma_s8(acc_x[nb * 2 + 0],  ah, bl + 0);
                mma_s8(acc_x[nb * 2 + 1],  ah, bl + 2);
                mma_s8(acc_x[nb * 2 + 0],  al, bh + 0);
                mma_s8(acc_x[nb * 2 + 1],  al, bh + 2);
            }
        }
        __syncthreads();
    }

    const int er = lane >> 2;
    const int ec = (lane & 3) * 2;
    const size_t row0 = m0 + wm * 16 + er;
    const size_t row1 = row0 + 8;
    const float sa0 = sA[row0];
    const float sa1 = sA[row1];
#pragma unroll
    for (int nbb = 0; nbb < 8; nbb++) {
        size_t col = n0 + wn * 64 + nbb * 8 + ec;
        float sb0 = __ldg(sB + col);
        float sb1 = __ldg(sB + col + 1);
        float b0 = __ldg(bias + col);
        float b1 = __ldg(bias + col + 1);
        float v00 = sa0 * sb0 * (16384.f * (float)acc_hh[nbb][0] + 128.f * (float)acc_x[nbb][0]) + b0;
        float v01 = sa0 * sb1 * (16384.f * (float)acc_hh[nbb][1] + 128.f * (float)acc_x[nbb][1]) + b1;
        float v10 = sa1 * sb0 * (16384.f * (float)acc_hh[nbb][2] + 128.f * (float)acc_x[nbb][2]) + b0;
        float v11 = sa1 * sb1 * (16384.f * (float)acc_hh[nbb][3] + 128.f * (float)acc_x[nbb][3]) + b1;
        *(float2*)(C + row0 * (size_t)N + col) = make_float2(v00, v01);
        *(float2*)(C + row1 * (size_t)N + col) = make_float2(v10, v11);
    }
}

// ---------------------------------------------------------------------------
// Flash attention: int8 QK^T + int8 PV (both two-level 3-term).
// ---------------------------------------------------------------------------
#define ATQ 64
#define ATK 64
#define LQ8 72    // b16-unit stride for int8 Q/K rows (144B)
#define LP8 40    // b16-unit stride for P / V^T rows (80B)
#define LSS 68

#define B_Q   0u          // Qh 9216, Ql @+9216
#define B_K   18432u      // +s*18432: Kh 9216, Kl @+9216
#define B_V   55296u      // +s*20480: Vh 10240 (128x80B), Vl @+10240
#define B_S   96256u      // 17408
#define B_P   113664u     // Ph 5120 (64x80B), Pl @+5120
#define B_SQ  123904u     // 256
#define B_SK  124160u     // 2*256
#define B_SV  124672u     // 2*512
#define B_AL  125696u
#define B_LI  125952u
#define B_KM  126208u     // 2*256
#define ATTN_SMEM_BYTES 126720

__global__ __launch_bounds__(256, 1) void attn_mma_kernel(
    const char* __restrict__ q8h, const char* __restrict__ q8l,
    const char* __restrict__ k8h, const char* __restrict__ k8l,
    const float* __restrict__ sq, const float* __restrict__ sk,
    const char* __restrict__ v8h, const char* __restrict__ v8l,
    const float* __restrict__ svt,
    const int* __restrict__ amask, const int* __restrict__ causal_ptr,
    float* __restrict__ outp)
{
    extern __shared__ __align__(16) char dsmem[];
    const uint32_t sb = smem_u32(dsmem);
    float* Ss  = (float*)(dsmem + B_S);
    float* sQs = (float*)(dsmem + B_SQ);
    float* sAl = (float*)(dsmem + B_AL);
    float* sLi = (float*)(dsmem + B_LI);

    const int tid  = threadIdx.x;
    const int lane = tid & 31;
    const int wid  = tid >> 5;
    const int wq   = wid & 3;
    const int wk   = wid >> 2;
    const int b  = blockIdx.x >> 4;
    const int h  = blockIdx.x & 15;
    const int q0 = blockIdx.y * ATQ;
    const int causal = *causal_ptr;

    const int ty = tid >> 4;
    const int tx = tid & 15;
    const float scale = 0.0883883476483184f;   // 1/sqrt(128)

    const int a_row = wq * 16 + (lane & 15);
    const int a_col = (lane >> 4) << 3;
    const int b_row = wk * 32 + ((lane >> 4) << 3) + (lane & 7);
    const int b_col = ((lane >> 3) & 1) << 3;
    const int bv_row = wk * 64 + ((lane >> 4) << 3) + (lane & 7);

    // prologue: Q int8 h/l + sQ
    const size_t gq8 = ((size_t)b * SS + q0) * 2048 + (size_t)h * 128;
#pragma unroll
    for (int it = 0; it < 2; it++) {
        int i = tid + it * 256;
        int r = i >> 3, sg = i & 7;
        uint32_t off = (uint32_t)(r * 144 + sg * 16);
        cp16(sb + B_Q + off,        q8h + gq8 + (size_t)r * 2048 + sg * 16);
        cp16(sb + B_Q + 9216 + off, q8l + gq8 + (size_t)r * 2048 + sg * 16);
    }
    if (tid < 16)
        cp16(sb + B_SQ + tid * 16, sq + (size_t)h * MM + (size_t)b * SS + q0 + tid * 4);

#define PREFETCH_KV(t, s) do {                                                   \
    size_t gk8 = ((size_t)b * SS + (size_t)(t) * ATK) * 2048 + (size_t)h * 128;  \
    for (int it = 0; it < 2; it++) {                                             \
        int i = tid + it * 256;                                                  \
        int r = i >> 3, sg = i & 7;                                              \
        uint32_t off = (uint32_t)(r * 144 + sg * 16);                            \
        cp16(sb + B_K + (s) * 18432u + off,        k8h + gk8 + (size_t)r * 2048 + sg * 16); \
        cp16(sb + B_K + (s) * 18432u + 9216 + off, k8l + gk8 + (size_t)r * 2048 + sg * 16); \
    }                                                                            \
    size_t gv8 = (size_t)(((b * HH + h) * 32) + (t)) * 8192;                     \
    for (int it = 0; it < 2; it++) {                                             \
        int i = tid + it * 256;                                                  \
        int r = i >> 2, sg = i & 3;                                              \
        uint32_t off = (uint32_t)(r * 80 + sg * 16);                             \
        cp16(sb + B_V + (s) * 20480u + off,         v8h + gv8 + (size_t)r * 64 + sg * 16); \
        cp16(sb + B_V + (s) * 20480u + 10240 + off, v8l + gv8 + (size_t)r * 64 + sg * 16); \
    }                                                                            \
    if (tid < 32)                                                                \
        cp16(sb + B_SV + (s) * 512u + tid * 16,                                  \
             svt + (size_t)(((b * HH + h) * 32) + (t)) * 128 + tid * 4);         \
    if (tid < 16)                                                                \
        cp16(sb + B_SK + (s) * 256u + tid * 16,                                  \
             sk + (size_t)h * MM + (size_t)b * SS + (size_t)(t) * ATK + tid * 4);\
    if (tid < 16)                                                                \
        cp16(sb + B_KM + (s) * 256u + tid * 16,                                  \
             amask + (size_t)b * SS + (size_t)(t) * ATK + tid * 4);              \
} while (0)

    float oacc[8][4];
#pragma unroll
    for (int j = 0; j < 8; j++)
#pragma unroll
        for (int e = 0; e < 4; e++) oacc[j][e] = 0.f;
    float mi[4], li[4];
#pragma unroll
    for (int i = 0; i < 4; i++) { mi[i] = -1e30f; li[i] = 0.f; }

    PREFETCH_KV(0, 0);
    CP_COMMIT();

    const int nTiles = SS / ATK;   // 32
    for (int t = 0; t < nTiles; t++) {
        const int s = t & 1;
        if (t + 1 < nTiles) {
            PREFETCH_KV(t + 1, s ^ 1);
            CP_COMMIT();
            CP_WAIT(1);
        } else {
            CP_WAIT(0);
        }
        __syncthreads();

        // ---- S = Q K^T (two-level int8, VALIDATED R14) ----
        const uint32_t uQh = sb + B_Q;
        const uint32_t uQl = uQh + 9216;
        const uint32_t uKh = sb + B_K + s * 18432u;
        const uint32_t uKl = uKh + 9216;

        int shh[4][4], sxx[4][4];
#pragma unroll
        for (int j = 0; j < 4; j++)
#pragma unroll
            for (int e = 0; e < 4; e++) { shh[j][e] = 0; sxx[j][e] = 0; }

#pragma unroll
        for (int ks = 0; ks < 4; ks++) {
            const int kk = ks * 16;
            uint32_t qh[4], ql[4];
            uint32_t aoff = (uint32_t)((a_row * LQ8 + kk + a_col) * 2);
            ldsm4(qh, uQh + aoff);
            ldsm4(ql, uQl + aoff);
#pragma unroll
            for (int nb = 0; nb < 2; nb++) {
                uint32_t boff = (uint32_t)(((b_row + nb * 16) * LQ8 + kk + b_col) * 2);
                uint32_t kh[4], kl[4];
                ldsm4(kh, uKh + boff);
                ldsm4(kl, uKl + boff);
                mma_s8(shh[nb * 2 + 0], qh, kh + 0);
                mma_s8(shh[nb * 2 + 1], qh, kh + 2);
                mma_s8(sxx[nb * 2 + 0], qh, kl + 0);
                mma_s8(sxx[nb * 2 + 1], qh, kl + 2);
                mma_s8(sxx[nb * 2 + 0], ql, kh + 0);
                mma_s8(sxx[nb * 2 + 1], ql, kh + 2);
            }
        }
        {
            const float* sKs = (const float*)(dsmem + B_SK + s * 256u);
            const int er = lane >> 2, ec = (lane & 3) * 2;
            const int srow = wq * 16 + er;
            const float sq0 = sQs[srow];
            const float sq1 = sQs[srow + 8];
#pragma unroll
            for (int j = 0; j < 4; j++) {
                int scol = wk * 32 + (j >> 1) * 16 + (j & 1) * 8 + ec;
                float f0 = sKs[scol], f1 = sKs[scol + 1];
                Ss[srow * LSS + scol] =
                    sq0 * f0 * (16384.f * (float)shh[j][0] + 128.f * (float)sxx[j][0]);
                Ss[srow * LSS + scol + 1] =
                    sq0 * f1 * (16384.f * (float)shh[j][1] + 128.f * (float)sxx[j][1]);
                Ss[(srow + 8) * LSS + scol] =
                    sq1 * f0 * (16384.f * (float)shh[j][2] + 128.f * (float)sxx[j][2]);
                Ss[(srow + 8) * LSS + scol + 1] =
                    sq1 * f1 * (16384.f * (float)shh[j][3] + 128.f * (float)sxx[j][3]);
            }
        }
        __syncthreads();

        // ---- softmax (validated) + P int8 quant (fixed scale 1/16256) ----
        {
            const int* km = (const int*)(dsmem + B_KM + s * 256u);
            float sf[4][4];
#pragma unroll
            for (int i = 0; i < 4; i++) {
                int qg = q0 + ty * 4 + i;
#pragma unroll
                for (int j = 0; j < 4; j++) {
                    int kg = t * ATK + tx * 4 + j;
                    bool ok = (km[tx * 4 + j] != 0) && (!causal || kg <= qg);
                    float sv = Ss[(ty * 4 + i) * LSS + tx * 4 + j];
                    sf[i][j] = ok ? sv * scale : -1e30f;
                }
            }
#pragma unroll
            for (int i = 0; i < 4; i++) {
                float tmax = fmaxf(fmaxf(sf[i][0], sf[i][1]), fmaxf(sf[i][2], sf[i][3]));
#pragma unroll
                for (int o = 8; o > 0; o >>= 1)
                    tmax = fmaxf(tmax, __shfl_xor_sync(0xffffffffu, tmax, o));
                float nm = fmaxf(mi[i], tmax);

                float p[4], rs = 0.f;
#pragma unroll
                for (int j = 0; j < 4; j++) {
                    p[j] = (sf[i][j] <= -1e29f) ? 0.f : __expf(sf[i][j] - nm);
                    rs += p[j];
                }
#pragma unroll
                for (int o = 8; o > 0; o >>= 1)
                    rs += __shfl_xor_sync(0xffffffffu, rs, o);

                float alpha = __expf(mi[i] - nm);
                li[i] = li[i] * alpha + rs;
                mi[i] = nm;
                sAl[ty * 4 + i] = alpha;

                char ph8[4], pl8[4];
#pragma unroll
                for (int j = 0; j < 4; j++) {
                    float tt = p[j] * 16256.f;
                    float hv = rintf(tt * (1.f / 128.f));
                    float lv = rintf(tt - 128.f * hv);
                    ph8[j] = (char)(int)hv;
                    pl8[j] = (char)(int)lv;
                }
                uint32_t poff = (uint32_t)((ty * 4 + i) * 80 + tx * 4);
                *(uint32_t*)(dsmem + B_P + poff)        = *(uint32_t*)ph8;
                *(uint32_t*)(dsmem + B_P + 5120 + poff) = *(uint32_t*)pl8;
            }
        }
        __syncthreads();

        // ---- O = O*alpha + P V (two-level int8, per-tile int32) ----
        {
            int phh[8][4], pxx[8][4];
#pragma unroll
            for (int j = 0; j < 8; j++)
#pragma unroll
                for (int e = 0; e < 4; e++) { phh[j][e] = 0; pxx[j][e] = 0; }

            const uint32_t uPh = sb + B_P;
            const uint32_t uPl = uPh + 5120;
            const uint32_t uVh = sb + B_V + s * 20480u;
            const uint32_t uVl = uVh + 10240;
#pragma unroll
            for (int ks = 0; ks < 2; ks++) {
                const int kk = ks * 16;   // b16 units = 32 tokens
                uint32_t ph[4], pl[4];
                uint32_t poff = (uint32_t)((a_row * LP8 + kk + a_col) * 2);
                ldsm4(ph, uPh + poff);
                ldsm4(pl, uPl + poff);
#pragma unroll
                for (int nb = 0; nb < 4; nb++) {
                    uint32_t voff = (uint32_t)(((bv_row + nb * 16) * LP8 + kk + b_col) * 2);
                    uint32_t vh[4], vl[4];
                    ldsm4(vh, uVh + voff);
                    ldsm4(vl, uVl + voff);
                    mma_s8(phh[nb * 2 + 0], ph, vh + 0);
                    mma_s8(phh[nb * 2 + 1], ph, vh + 2);
                    mma_s8(pxx[nb * 2 + 0], ph, vl + 0);
                    mma_s8(pxx[nb * 2 + 1], ph, vl + 2);
                    mma_s8(pxx[nb * 2 + 0], pl, vh + 0);
                    mma_s8(pxx[nb * 2 + 1], pl, vh + 2);
                }
            }

            const float* sVd = (const float*)(dsmem + B_SV + s * 512u);
            const int er = lane >> 2, ec = (lane & 3) * 2;
            const float a0 = sAl[wq * 16 + er];
            const float a1 = sAl[wq * 16 + er + 8];
            const float inv16256 = 1.f / 16256.f;
#pragma unroll
            for (int j = 0; j < 8; j++) {
                int col = wk * 64 + j * 8 + ec;
                float sv0 = sVd[col] * inv16256;
                float sv1 = sVd[col + 1] * inv16256;
                oacc[j][0] = oacc[j][0] * a0 +
                    sv0 * (16384.f * (float)phh[j][0] + 128.f * (float)pxx[j][0]);
                oacc[j][1] = oacc[j][1] * a0 +
                    sv1 * (16384.f * (float)phh[j][1] + 128.f * (float)pxx[j][1]);
                oacc[j][2] = oacc[j][2] * a1 +
                    sv0 * (16384.f * (float)phh[j][2] + 128.f * (float)pxx[j][2]);
                oacc[j][3] = oacc[j][3] * a1 +
                    sv1 * (16384.f * (float)phh[j][3] + 128.f * (float)pxx[j][3]);
            }
        }
        __syncthreads();
    }

    sLi[ty * 4 + 0] = (li[0] > 0.f) ? 1.f / li[0] : 0.f;
    sLi[ty * 4 + 1] = (li[1] > 0.f) ? 1.f / li[1] : 0.f;
    sLi[ty * 4 + 2] = (li[2] > 0.f) ? 1.f / li[2] : 0.f;
    sLi[ty * 4 + 3] = (li[3] > 0.f) ? 1.f / li[3] : 0.f;
    __syncthreads();

    {
        const int er = lane >> 2, ec = (lane & 3) * 2;
        float inv0 = sLi[wq * 16 + er];
        float inv1 = sLi[wq * 16 + er + 8];
        size_t grow0 = ((size_t)b * SS + q0 + wq * 16 + er) * 2048;
        size_t grow1 = grow0 + (size_t)8 * 2048;
#pragma unroll
        for (int j = 0; j < 8; j++) {
            size_t colg = (size_t)h * 128 + wk * 64 + j * 8 + ec;
            *(float2*)(outp + grow0 + colg) =
                make_float2(oacc[j][0] * inv0, oacc[j][1] * inv0);
            *(float2*)(outp + grow1 + colg) =
                make_float2(oacc[j][2] * inv1, oacc[j][3] * inv1);
        }
    }
}

// ---------------------------------------------------------------------------
// Launch
// ---------------------------------------------------------------------------
extern "C" void kernel_launch(void* const* d_in, const int* in_sizes, int n_in,
                              void* d_out, int out_size)
{
    const float* x_q    = (const float*)d_in[0];
    const float* x_kv   = (const float*)d_in[1];
    const float* Wq     = (const float*)d_in[2];
    const float* bq     = (const float*)d_in[3];
    const float* Wk     = (const float*)d_in[4];
    const float* bk     = (const float*)d_in[5];
    const float* Wv     = (const float*)d_in[6];
    const float* bv     = (const float*)d_in[7];
    const float* Wo     = (const float*)d_in[8];
    const float* bo     = (const float*)d_in[9];
    const float* angles = (const float*)d_in[10];
    const int*   amask  = (const int*)d_in[11];
    const int*   causal = (const int*)d_in[12];
    const int*   k_rope = (const int*)d_in[13];
    float* out = (float*)d_out;

    float *q, *k, *v, *attn;
    cudaGetSymbolAddress((void**)&q,    g_q);
    cudaGetSymbolAddress((void**)&k,    g_k);
    cudaGetSymbolAddress((void**)&v,    g_v);
    cudaGetSymbolAddress((void**)&attn, g_attn);

    char *xq_h, *xq_l, *xkv_h, *xkv_l, *at_h, *at_l;
    char *wq_h, *wq_l, *wk_h, *wk_l, *wv_h, *wv_l, *wo_h, *wo_l;
    float *sxq, *sxkv, *sat, *swq, *swk, *swv, *swo;
    cudaGetSymbolAddress((void**)&xq_h,  g_xq_h);
    cudaGetSymbolAddress((void**)&xq_l,  g_xq_l);
    cudaGetSymbolAddress((void**)&xkv_h, g_xkv_h);
    cudaGetSymbolAddress((void**)&xkv_l, g_xkv_l);
    cudaGetSymbolAddress((void**)&at_h,  g_at_h);
    cudaGetSymbolAddress((void**)&at_l,  g_at_l);
    cudaGetSymbolAddress((void**)&wq_h,  g_wq_h);
    cudaGetSymbolAddress((void**)&wq_l,  g_wq_l);
    cudaGetSymbolAddress((void**)&wk_h,  g_wk_h);
    cudaGetSymbolAddress((void**)&wk_l,  g_wk_l);
    cudaGetSymbolAddress((void**)&wv_h,  g_wv_h);
    cudaGetSymbolAddress((void**)&wv_l,  g_wv_l);
    cudaGetSymbolAddress((void**)&wo_h,  g_wo_h);
    cudaGetSymbolAddress((void**)&wo_l,  g_wo_l);
    cudaGetSymbolAddress((void**)&sxq,  g_sxq);
    cudaGetSymbolAddress((void**)&sxkv, g_sxkv);
    cudaGetSymbolAddress((void**)&sat,  g_sat);
    cudaGetSymbolAddress((void**)&swq,  g_swq);
    cudaGetSymbolAddress((void**)&swk,  g_swk);
    cudaGetSymbolAddress((void**)&swv,  g_swv);
    cudaGetSymbolAddress((void**)&swo,  g_swo);

    char *q8h, *q8l, *k8h, *k8l, *v8h, *v8l;
    float *sq8, *sk8, *svt;
    cudaGetSymbolAddress((void**)&q8h, g_q8h);
    cudaGetSymbolAddress((void**)&q8l, g_q8l);
    cudaGetSymbolAddress((void**)&k8h, g_k8h);
    cudaGetSymbolAddress((void**)&k8l, g_k8l);
    cudaGetSymbolAddress((void**)&v8h, g_v8h);
    cudaGetSymbolAddress((void**)&v8l, g_v8l);
    cudaGetSymbolAddress((void**)&sq8, g_sq8);
    cudaGetSymbolAddress((void**)&sk8, g_sk8);
    cudaGetSymbolAddress((void**)&svt, g_svt);

    const int M = MM, N = EE, K = EE;

    cudaFuncSetAttribute(gemm_s8_kernel,
                         cudaFuncAttributeMaxDynamicSharedMemorySize, GEMM_SMEM_BYTES);
    cudaFuncSetAttribute(attn_mma_kernel,
                         cudaFuncAttributeMaxDynamicSharedMemorySize, ATTN_SMEM_BYTES);
    dim3 gGrid(N / GBN, M / GBM);   // (16, 64)

    // quantize inputs + weights
    quant_rows_kernel<<<MM, 256>>>(x_q,  xq_h,  xq_l,  sxq);
    quant_rows_kernel<<<MM, 256>>>(x_kv, xkv_h, xkv_l, sxkv);
    quant_rows_kernel<<<EE, 256>>>(Wq, wq_h, wq_l, swq);
    quant_rows_kernel<<<EE, 256>>>(Wk, wk_h, wk_l, swk);
    quant_rows_kernel<<<EE, 256>>>(Wv, wv_h, wv_l, swv);
    quant_rows_kernel<<<EE, 256>>>(Wo, wo_h, wo_l, swo);

    // projections (all fp32 out)
    gemm_s8_kernel<<<gGrid, 512, GEMM_SMEM_BYTES>>>(
        xq_h,  xq_l,  wq_h, wq_l, sxq,  swq, bq, q, M, N, K);
    gemm_s8_kernel<<<gGrid, 512, GEMM_SMEM_BYTES>>>(
        xkv_h, xkv_l, wk_h, wk_l, sxkv, swk, bk, k, M, N, K);
    gemm_s8_kernel<<<gGrid, 512, GEMM_SMEM_BYTES>>>(
        xkv_h, xkv_l, wv_h, wv_l, sxkv, swv, bv, v, M, N, K);

    // fused rope + int8 quant (q always; k gated), V tile-column quant
    const int rqBlocks = BB * SS * HH / 4;   // 32768
    rope_quant_kernel<<<rqBlocks, 128>>>(q, angles, k_rope, 1, q8h, q8l, sq8);
    rope_quant_kernel<<<rqBlocks, 128>>>(k, angles, k_rope, 0, k8h, k8l, sk8);
    vquant_kernel<<<BB * HH * 32, 128>>>(v, v8h, v8l, svt);

    // attention (full int8 MMA path, fp32 out)
    dim3 aGrid(BB * HH, SS / ATQ);   // (64, 32)
    attn_mma_kernel<<<aGrid, 256, ATTN_SMEM_BYTES>>>(
        q8h, q8l, k8h, k8l, sq8, sk8, v8h, v8l, svt, amask, causal, attn);

    // re-quantize attention output, final projection
    quant_rows_kernel<<<MM, 256>>>(attn, at_h, at_l, sat);
    gemm_s8_kernel<<<gGrid, 512, GEMM_SMEM_BYTES>>>(
        at_h, at_l, wo_h, wo_l, sat, swo, bo, out, M, N, K);
}

// round 17
// speedup vs baseline: 1.1063x; 1.1063x over previous
#include <cuda_runtime.h>
#include <cuda_bf16.h>
#include <cstdint>
#include <math.h>

// Problem constants
#define BB 4
#define SS 2048
#define EE 2048
#define HH 16
#define DD 128
#define DH 64   // DD/2

#define MM (BB * SS)              // 8192
#define NELEM ((size_t)MM * EE)   // 16,777,216
#define WELEM ((size_t)EE * EE)   // 4,194,304

// ---------------------------------------------------------------------------
// Scratch (device globals — no allocation allowed in kernel_launch)
// ---------------------------------------------------------------------------
__device__ float g_q[NELEM];
__device__ float g_k[NELEM];
__device__ float g_v[NELEM];
__device__ float g_attn[NELEM];

__device__ char g_xq_h[NELEM],  g_xq_l[NELEM];
__device__ char g_xkv_h[NELEM], g_xkv_l[NELEM];
__device__ char g_at_h[NELEM],  g_at_l[NELEM];
__device__ char g_wq_h[WELEM], g_wq_l[WELEM];
__device__ char g_wk_h[WELEM], g_wk_l[WELEM];
__device__ char g_wv_h[WELEM], g_wv_l[WELEM];
__device__ char g_wo_h[WELEM], g_wo_l[WELEM];
__device__ float g_sxq[MM], g_sxkv[MM], g_sat[MM];
__device__ float g_swq[EE], g_swk[EE], g_swv[EE], g_swo[EE];

// attention operands
__device__ char g_q8h[NELEM], g_q8l[NELEM];
__device__ char g_k8h[NELEM], g_k8l[NELEM];
__device__ float g_sq8[(size_t)HH * MM], g_sk8[(size_t)HH * MM];  // [H][M]
__device__ char g_v8h[NELEM], g_v8l[NELEM];          // transposed tiles
__device__ float g_svt[(size_t)BB * HH * 32 * 128];  // per (b,h,tile,d)

// ---------------------------------------------------------------------------
// helpers
// ---------------------------------------------------------------------------
__device__ __forceinline__ uint32_t smem_u32(const void* p) {
    uint32_t a;
    asm("{ .reg .u64 t; cvta.to.shared.u64 t, %1; cvt.u32.u64 %0, t; }"
        : "=r"(a) : "l"(p));
    return a;
}

__device__ __forceinline__ void ldsm4(uint32_t* r, uint32_t addr) {
    asm volatile("ldmatrix.sync.aligned.m8n8.x4.shared.b16 {%0,%1,%2,%3}, [%4];"
        : "=r"(r[0]), "=r"(r[1]), "=r"(r[2]), "=r"(r[3]) : "r"(addr));
}

__device__ __forceinline__ void mma_s8(int* d, const uint32_t* a,
                                       const uint32_t* b) {
    asm volatile(
        "mma.sync.aligned.m16n8k32.row.col.s32.s8.s8.s32 "
        "{%0,%1,%2,%3}, {%4,%5,%6,%7}, {%8,%9}, {%0,%1,%2,%3};"
        : "+r"(d[0]), "+r"(d[1]), "+r"(d[2]), "+r"(d[3])
        : "r"(a[0]), "r"(a[1]), "r"(a[2]), "r"(a[3]), "r"(b[0]), "r"(b[1]));
}

__device__ __forceinline__ void cp16(uint32_t dst, const void* src) {
    asm volatile("cp.async.ca.shared.global [%0], [%1], 16;"
        :: "r"(dst), "l"((uint64_t)__cvta_generic_to_global(src)));
}
#define CP_COMMIT() asm volatile("cp.async.commit_group;")
#define CP_WAIT(n)  asm volatile("cp.async.wait_group %0;" :: "n"(n))

// ---------------------------------------------------------------------------
// Quantize rows: fp32 [rows, 2048] -> int8 h,l with per-row scale.
// ---------------------------------------------------------------------------
__global__ __launch_bounds__(256) void quant_rows_kernel(
    const float* __restrict__ src, char* __restrict__ h8,
    char* __restrict__ l8, float* __restrict__ scale)
{
    const int row = blockIdx.x;
    const int tid = threadIdx.x;
    const float* r = src + (size_t)row * 2048 + tid * 8;
    float4 v0 = *(const float4*)(r);
    float4 v1 = *(const float4*)(r + 4);
    float w[8] = {v0.x, v0.y, v0.z, v0.w, v1.x, v1.y, v1.z, v1.w};

    float m = 0.f;
#pragma unroll
    for (int e = 0; e < 8; e++) m = fmaxf(m, fabsf(w[e]));
#pragma unroll
    for (int o = 16; o > 0; o >>= 1)
        m = fmaxf(m, __shfl_xor_sync(0xffffffffu, m, o));

    __shared__ float red[8];
    __shared__ float ssc;
    if ((tid & 31) == 0) red[tid >> 5] = m;
    __syncthreads();
    if (tid == 0) {
        float mm = red[0];
#pragma unroll
        for (int i = 1; i < 8; i++) mm = fmaxf(mm, red[i]);
        float s = (mm > 0.f) ? mm / 16256.f : 1.f;
        ssc = s;
        scale[row] = s;
    }
    __syncthreads();
    const float inv = 1.f / ssc;

    char h[8], l[8];
#pragma unroll
    for (int e = 0; e < 8; e++) {
        float t = w[e] * inv;
        float hq = rintf(t * (1.f / 128.f));
        float lq = rintf(t - 128.f * hq);
        h[e] = (char)(int)hq;
        l[e] = (char)(int)lq;
    }
    size_t o8 = (size_t)row * 2048 + tid * 8;
    *(uint2*)(h8 + o8) = *(uint2*)h;
    *(uint2*)(l8 + o8) = *(uint2*)l;
}

// ---------------------------------------------------------------------------
// Fused RoPE + two-level int8 quant per (b,s,h) head-row. scale: [H][M].
// ---------------------------------------------------------------------------
__global__ __launch_bounds__(128) void rope_quant_kernel(
    const float* __restrict__ x, const float* __restrict__ angles,
    const int* __restrict__ flag, int always,
    char* __restrict__ h8, char* __restrict__ l8, float* __restrict__ scale)
{
    const int wid  = threadIdx.x >> 5;
    const int lane = threadIdx.x & 31;
    const int g = blockIdx.x * 4 + wid;
    const int b    = g / (SS * HH);
    const int rem  = g % (SS * HH);
    const int spos = rem / HH;
    const int h    = rem % HH;
    const size_t base = (size_t)g * DD;
    const bool doRope = always || (*flag != 0);

    const int d0 = lane, d1 = lane + 32;
    float x1a = x[base + d0], x2a = x[base + d0 + DH];
    float x1b = x[base + d1], x2b = x[base + d1 + DH];
    float y[4];
    if (doRope) {
        float sn0 = angles[(size_t)spos * DH + d0];
        float cs0 = angles[(size_t)SS * DH + (size_t)spos * DH + d0];
        float sn1 = angles[(size_t)spos * DH + d1];
        float cs1 = angles[(size_t)SS * DH + (size_t)spos * DH + d1];
        y[0] = x1a * cs0 - x2a * sn0;
        y[1] = x1a * sn0 + x2a * cs0;
        y[2] = x1b * cs1 - x2b * sn1;
        y[3] = x1b * sn1 + x2b * cs1;
    } else {
        y[0] = x1a; y[1] = x2a; y[2] = x1b; y[3] = x2b;
    }

    float m = fmaxf(fmaxf(fabsf(y[0]), fabsf(y[1])),
                    fmaxf(fabsf(y[2]), fabsf(y[3])));
#pragma unroll
    for (int o = 16; o > 0; o >>= 1)
        m = fmaxf(m, __shfl_xor_sync(0xffffffffu, m, o));
    float s = (m > 0.f) ? m / 16256.f : 1.f;
    float inv = 1.f / s;

    char hq[4], lq[4];
#pragma unroll
    for (int e = 0; e < 4; e++) {
        float t = y[e] * inv;
        float hv = rintf(t * (1.f / 128.f));
        float lv = rintf(t - 128.f * hv);
        hq[e] = (char)(int)hv;
        lq[e] = (char)(int)lv;
    }
    h8[base + d0]      = hq[0];
    h8[base + d0 + DH] = hq[1];
    h8[base + d1]      = hq[2];
    h8[base + d1 + DH] = hq[3];
    l8[base + d0]      = lq[0];
    l8[base + d0 + DH] = lq[1];
    l8[base + d1]      = lq[2];
    l8[base + d1 + DH] = lq[3];
    if (lane == 0)
        scale[(size_t)h * MM + (size_t)b * SS + spos] = s;
}

// ---------------------------------------------------------------------------
// V quant: fp32 V -> transposed int8 tiles (per (b,h,tile,d) scales).
// ---------------------------------------------------------------------------
__global__ __launch_bounds__(128) void vquant_kernel(
    const float* __restrict__ v, char* __restrict__ v8h,
    char* __restrict__ v8l, float* __restrict__ svt)
{
    const int g = blockIdx.x;            // (b*HH+h)*32 + tile
    const int tile = g & 31;
    const int bh = g >> 5;
    const int b = bh >> 4, h = bh & 15;
    const int d = threadIdx.x;

    const float* src = v + ((size_t)b * SS + tile * 64) * 2048 + h * 128 + d;
    float vals[64];
    float m = 0.f;
#pragma unroll
    for (int t = 0; t < 64; t++) {
        vals[t] = src[(size_t)t * 2048];
        m = fmaxf(m, fabsf(vals[t]));
    }
    float s = (m > 0.f) ? m / 16256.f : 1.f;
    float inv = 1.f / s;

    char h8[64], l8[64];
#pragma unroll
    for (int t = 0; t < 64; t++) {
        float tt = vals[t] * inv;
        float hv = rintf(tt * (1.f / 128.f));
        float lv = rintf(tt - 128.f * hv);
        h8[t] = (char)(int)hv;
        l8[t] = (char)(int)lv;
    }
    size_t ob = (size_t)g * 8192 + (size_t)d * 64;
#pragma unroll
    for (int sg = 0; sg < 4; sg++) {
        *(uint4*)(v8h + ob + sg * 16) = *(uint4*)(h8 + sg * 16);
        *(uint4*)(v8l + ob + sg * 16) = *(uint4*)(l8 + sg * 16);
    }
    svt[(size_t)g * 128 + d] = s;
}

// ---------------------------------------------------------------------------
// int8 tensor-core GEMM (VALIDATED R11)
// ---------------------------------------------------------------------------
#define GBM 128
#define GBN 128
#define GBK 64
#define LDS 40
#define BUFB (GBM * LDS * 2)       // 10240
#define GEMM_SMEM_BYTES (BUFB * 8)

__global__ __launch_bounds__(512) void gemm_s8_kernel(
    const char* __restrict__ Ah, const char* __restrict__ Al,
    const char* __restrict__ Bh, const char* __restrict__ Bl,
    const float* __restrict__ sA, const float* __restrict__ sB,
    const float* __restrict__ bias, float* __restrict__ C,
    int M, int N, int K)
{
    extern __shared__ __align__(16) char dsmem[];
    const uint32_t sb = smem_u32(dsmem);

    const int tid  = threadIdx.x;
    const int lane = tid & 31;
    const int wid  = tid >> 5;
    const int wm   = wid & 7;
    const int wn   = wid >> 3;
    const size_t m0 = (size_t)blockIdx.y * GBM;
    const size_t n0 = (size_t)blockIdx.x * GBN;

    int acc_hh[8][4], acc_x[8][4];
#pragma unroll
    for (int j = 0; j < 8; j++)
#pragma unroll
        for (int e = 0; e < 4; e++) { acc_hh[j][e] = 0; acc_x[j][e] = 0; }

    const int ra = tid >> 2;
    const int ca = tid & 3;

    const int a_row = wm * 16 + (lane & 15);
    const int a_col = (lane >> 4) << 3;
    const int b_row = wn * 64 + ((lane >> 4) << 3) + (lane & 7);
    const int b_col = ((lane >> 3) & 1) << 3;

    const int nChunks = K / GBK;

#define PREFETCH8(c, s) do {                                                    \
    size_t ca64 = (size_t)(c) * GBK;                                            \
    uint32_t d = (uint32_t)(ra * 80 + ca * 16);                                 \
    cp16(sb + (0 + (s)) * BUFB + d, Ah + (m0 + ra) * (size_t)K + ca64 + ca * 16); \
    cp16(sb + (2 + (s)) * BUFB + d, Al + (m0 + ra) * (size_t)K + ca64 + ca * 16); \
    cp16(sb + (4 + (s)) * BUFB + d, Bh + (n0 + ra) * (size_t)K + ca64 + ca * 16); \
    cp16(sb + (6 + (s)) * BUFB + d, Bl + (n0 + ra) * (size_t)K + ca64 + ca * 16); \
} while (0)

    PREFETCH8(0, 0);
    CP_COMMIT();

    for (int c = 0; c < nChunks; c++) {
        const int s = c & 1;
        if (c + 1 < nChunks) {
            PREFETCH8(c + 1, s ^ 1);
            CP_COMMIT();
            CP_WAIT(1);
        } else {
            CP_WAIT(0);
        }
        __syncthreads();

        const uint32_t uAh = sb + (0 + s) * BUFB;
        const uint32_t uAl = sb + (2 + s) * BUFB;
        const uint32_t uBh = sb + (4 + s) * BUFB;
        const uint32_t uBl = sb + (6 + s) * BUFB;

#pragma unroll
        for (int ks = 0; ks < 2; ks++) {
            const int kk = ks * 16;
            uint32_t ah[4], al[4];
            uint32_t aoff = (uint32_t)((a_row * LDS + kk + a_col) * 2);
            ldsm4(ah, uAh + aoff);
            ldsm4(al, uAl + aoff);
#pragma unroll
            for (int nb = 0; nb < 4; nb++) {
                uint32_t boff = (uint32_t)(((b_row + nb * 16) * LDS + kk + b_col) * 2);
                uint32_t bh[4], bl[4];
                ldsm4(bh, uBh + boff);
                ldsm4(bl, uBl + boff);
                mma_s8(acc_hh[nb * 2 + 0], ah, bh + 0);
                mma_s8(acc_hh[nb * 2 + 1], ah, bh + 2);
                mma_s8(acc_x[nb * 2 + 0],  ah, bl + 0);
                mma_s8(acc_x[nb * 2 + 1],  ah, bl + 2);
                mma_s8(acc_x[nb * 2 + 0],  al, bh + 0);
                mma_s8(acc_x[nb * 2 + 1],  al, bh + 2);
            }
        }
        __syncthreads();
    }

    const int er = lane >> 2;
    const int ec = (lane & 3) * 2;
    const size_t row0 = m0 + wm * 16 + er;
    const size_t row1 = row0 + 8;
    const float sa0 = sA[row0];
    const float sa1 = sA[row1];
#pragma unroll
    for (int nbb = 0; nbb < 8; nbb++) {
        size_t col = n0 + wn * 64 + nbb * 8 + ec;
        float sb0 = __ldg(sB + col);
        float sb1 = __ldg(sB + col + 1);
        float b0 = __ldg(bias + col);
        float b1 = __ldg(bias + col + 1);
        float v00 = sa0 * sb0 * (16384.f * (float)acc_hh[nbb][0] + 128.f * (float)acc_x[nbb][0]) + b0;
        float v01 = sa0 * sb1 * (16384.f * (float)acc_hh[nbb][1] + 128.f * (float)acc_x[nbb][1]) + b1;
        float v10 = sa1 * sb0 * (16384.f * (float)acc_hh[nbb][2] + 128.f * (float)acc_x[nbb][2]) + b0;
        float v11 = sa1 * sb1 * (16384.f * (float)acc_hh[nbb][3] + 128.f * (float)acc_x[nbb][3]) + b1;
        *(float2*)(C + row0 * (size_t)N + col) = make_float2(v00, v01);
        *(float2*)(C + row1 * (size_t)N + col) = make_float2(v10, v11);
    }
}

// ---------------------------------------------------------------------------
// Flash attention: int8 QK^T + int8 PV (VALIDATED R15 math), single-stage V,
// 2 CTAs/SM (smem 105728 B, __launch_bounds__(256,2)).
// ---------------------------------------------------------------------------
#define ATQ 64
#define ATK 64
#define LQ8 72    // b16-unit stride for int8 Q/K rows (144B)
#define LP8 40    // b16-unit stride for P / V^T rows (80B)
#define LSS 68

#define B_Q   0u          // Qh 9216, Ql @+9216
#define B_K   18432u      // +s*18432 (double-staged)
#define B_V   55296u      // single stage: Vh 10240, Vl @+10240
#define B_S   75776u      // 17408
#define B_P   93184u      // Ph 5120, Pl @+5120
#define B_SQ  103424u     // 256
#define B_SK  103680u     // 2*256
#define B_SV  104192u     // 512 (single stage)
#define B_AL  104704u
#define B_LI  104960u
#define B_KM  105216u     // 2*256
#define ATTN_SMEM_BYTES 105728

__global__ __launch_bounds__(256, 2) void attn_mma_kernel(
    const char* __restrict__ q8h, const char* __restrict__ q8l,
    const char* __restrict__ k8h, const char* __restrict__ k8l,
    const float* __restrict__ sq, const float* __restrict__ sk,
    const char* __restrict__ v8h, const char* __restrict__ v8l,
    const float* __restrict__ svt,
    const int* __restrict__ amask, const int* __restrict__ causal_ptr,
    float* __restrict__ outp)
{
    extern __shared__ __align__(16) char dsmem[];
    const uint32_t sb = smem_u32(dsmem);
    float* Ss  = (float*)(dsmem + B_S);
    float* sQs = (float*)(dsmem + B_SQ);
    float* sAl = (float*)(dsmem + B_AL);
    float* sLi = (float*)(dsmem + B_LI);

    const int tid  = threadIdx.x;
    const int lane = tid & 31;
    const int wid  = tid >> 5;
    const int wq   = wid & 3;
    const int wk   = wid >> 2;
    const int b  = blockIdx.x >> 4;
    const int h  = blockIdx.x & 15;
    const int q0 = blockIdx.y * ATQ;
    const int causal = *causal_ptr;

    const int ty = tid >> 4;
    const int tx = tid & 15;
    const float scale = 0.0883883476483184f;   // 1/sqrt(128)

    const int a_row = wq * 16 + (lane & 15);
    const int a_col = (lane >> 4) << 3;
    const int b_row = wk * 32 + ((lane >> 4) << 3) + (lane & 7);
    const int b_col = ((lane >> 3) & 1) << 3;
    const int bv_row = wk * 64 + ((lane >> 4) << 3) + (lane & 7);

    // prologue: Q int8 h/l + sQ  (group 0)
    const size_t gq8 = ((size_t)b * SS + q0) * 2048 + (size_t)h * 128;
#pragma unroll
    for (int it = 0; it < 2; it++) {
        int i = tid + it * 256;
        int r = i >> 3, sg = i & 7;
        uint32_t off = (uint32_t)(r * 144 + sg * 16);
        cp16(sb + B_Q + off,        q8h + gq8 + (size_t)r * 2048 + sg * 16);
        cp16(sb + B_Q + 9216 + off, q8l + gq8 + (size_t)r * 2048 + sg * 16);
    }
    if (tid < 16)
        cp16(sb + B_SQ + tid * 16, sq + (size_t)h * MM + (size_t)b * SS + q0 + tid * 4);
    CP_COMMIT();

#define PREFETCH_K(t, s) do {                                                    \
    size_t gk8 = ((size_t)b * SS + (size_t)(t) * ATK) * 2048 + (size_t)h * 128;  \
    for (int it = 0; it < 2; it++) {                                             \
        int i = tid + it * 256;                                                  \
        int r = i >> 3, sg = i & 7;                                              \
        uint32_t off = (uint32_t)(r * 144 + sg * 16);                            \
        cp16(sb + B_K + (s) * 18432u + off,        k8h + gk8 + (size_t)r * 2048 + sg * 16); \
        cp16(sb + B_K + (s) * 18432u + 9216 + off, k8l + gk8 + (size_t)r * 2048 + sg * 16); \
    }                                                                            \
    if (tid < 16)                                                                \
        cp16(sb + B_SK + (s) * 256u + tid * 16,                                  \
             sk + (size_t)h * MM + (size_t)b * SS + (size_t)(t) * ATK + tid * 4);\
    if (tid < 16)                                                                \
        cp16(sb + B_KM + (s) * 256u + tid * 16,                                  \
             amask + (size_t)b * SS + (size_t)(t) * ATK + tid * 4);              \
} while (0)

#define PREFETCH_V(t) do {                                                       \
    size_t gv8 = (size_t)(((b * HH + h) * 32) + (t)) * 8192;                     \
    for (int it = 0; it < 2; it++) {                                             \
        int i = tid + it * 256;                                                  \
        int r = i >> 2, sg = i & 3;                                              \
        uint32_t off = (uint32_t)(r * 80 + sg * 16);                             \
        cp16(sb + B_V + off,         v8h + gv8 + (size_t)r * 64 + sg * 16);      \
        cp16(sb + B_V + 10240 + off, v8l + gv8 + (size_t)r * 64 + sg * 16);      \
    }                                                                            \
    if (tid < 32)                                                                \
        cp16(sb + B_SV + tid * 16,                                               \
             svt + (size_t)(((b * HH + h) * 32) + (t)) * 128 + tid * 4);         \
} while (0)

    PREFETCH_K(0, 0);
    CP_COMMIT();   // group 1

    float oacc[8][4];
#pragma unroll
    for (int j = 0; j < 8; j++)
#pragma unroll
        for (int e = 0; e < 4; e++) oacc[j][e] = 0.f;
    float mi[4], li[4];
#pragma unroll
    for (int i = 0; i < 4; i++) { mi[i] = -1e30f; li[i] = 0.f; }

    const int nTiles = SS / ATK;   // 32
    for (int t = 0; t < nTiles; t++) {
        const int s = t & 1;

        __syncthreads();           // PV(t-1) done everywhere -> V buffer free
        PREFETCH_V(t);
        CP_COMMIT();               // group V(t)
        if (t + 1 < nTiles) {
            PREFETCH_K(t + 1, s ^ 1);
            CP_COMMIT();           // group K(t+1)
            CP_WAIT(2);            // K(t) and older arrived
        } else {
            CP_WAIT(1);            // K(t) arrived (only V(t) may be pending)
        }
        __syncthreads();           // K(t)/sk/mask visible to all warps

        // ---- S = Q K^T (two-level int8, VALIDATED) ----
        const uint32_t uQh = sb + B_Q;
        const uint32_t uQl = uQh + 9216;
        const uint32_t uKh = sb + B_K + s * 18432u;
        const uint32_t uKl = uKh + 9216;

        int shh[4][4], sxx[4][4];
#pragma unroll
        for (int j = 0; j < 4; j++)
#pragma unroll
            for (int e = 0; e < 4; e++) { shh[j][e] = 0; sxx[j][e] = 0; }

#pragma unroll
        for (int ks = 0; ks < 4; ks++) {
            const int kk = ks * 16;
            uint32_t qh[4], ql[4];
            uint32_t aoff = (uint32_t)((a_row * LQ8 + kk + a_col) * 2);
            ldsm4(qh, uQh + aoff);
            ldsm4(ql, uQl + aoff);
#pragma unroll
            for (int nb = 0; nb < 2; nb++) {
                uint32_t boff = (uint32_t)(((b_row + nb * 16) * LQ8 + kk + b_col) * 2);
                uint32_t kh[4], kl[4];
                ldsm4(kh, uKh + boff);
                ldsm4(kl, uKl + boff);
                mma_s8(shh[nb * 2 + 0], qh, kh + 0);
                mma_s8(shh[nb * 2 + 1], qh, kh + 2);
                mma_s8(sxx[nb * 2 + 0], qh, kl + 0);
                mma_s8(sxx[nb * 2 + 1], qh, kl + 2);
                mma_s8(sxx[nb * 2 + 0], ql, kh + 0);
                mma_s8(sxx[nb * 2 + 1], ql, kh + 2);
            }
        }
        {
            const float* sKs = (const float*)(dsmem + B_SK + s * 256u);
            const int er = lane >> 2, ec = (lane & 3) * 2;
            const int srow = wq * 16 + er;
            const float sq0 = sQs[srow];
            const float sq1 = sQs[srow + 8];
#pragma unroll
            for (int j = 0; j < 4; j++) {
                int scol = wk * 32 + (j >> 1) * 16 + (j & 1) * 8 + ec;
                float f0 = sKs[scol], f1 = sKs[scol + 1];
                Ss[srow * LSS + scol] =
                    sq0 * f0 * (16384.f * (float)shh[j][0] + 128.f * (float)sxx[j][0]);
                Ss[srow * LSS + scol + 1] =
                    sq0 * f1 * (16384.f * (float)shh[j][1] + 128.f * (float)sxx[j][1]);
                Ss[(srow + 8) * LSS + scol] =
                    sq1 * f0 * (16384.f * (float)shh[j][2] + 128.f * (float)sxx[j][2]);
                Ss[(srow + 8) * LSS + scol + 1] =
                    sq1 * f1 * (16384.f * (float)shh[j][3] + 128.f * (float)sxx[j][3]);
            }
        }
        __syncthreads();

        // ---- softmax (VALIDATED R15 ty/tx path) + P int8 quant ----
        {
            const int* km = (const int*)(dsmem + B_KM + s * 256u);
            float sf[4][4];
#pragma unroll
            for (int i = 0; i < 4; i++) {
                int qg = q0 + ty * 4 + i;
#pragma unroll
                for (int j = 0; j < 4; j++) {
                    int kg = t * ATK + tx * 4 + j;
                    bool ok = (km[tx * 4 + j] != 0) && (!causal || kg <= qg);
                    float sv = Ss[(ty * 4 + i) * LSS + tx * 4 + j];
                    sf[i][j] = ok ? sv * scale : -1e30f;
                }
            }
#pragma unroll
            for (int i = 0; i < 4; i++) {
                float tmax = fmaxf(fmaxf(sf[i][0], sf[i][1]), fmaxf(sf[i][2], sf[i][3]));
#pragma unroll
                for (int o = 8; o > 0; o >>= 1)
                    tmax = fmaxf(tmax, __shfl_xor_sync(0xffffffffu, tmax, o));
                float nm = fmaxf(mi[i], tmax);

                float p[4], rs = 0.f;
#pragma unroll
                for (int j = 0; j < 4; j++) {
                    p[j] = (sf[i][j] <= -1e29f) ? 0.f : __expf(sf[i][j] - nm);
                    rs += p[j];
                }
#pragma unroll
                for (int o = 8; o > 0; o >>= 1)
                    rs += __shfl_xor_sync(0xffffffffu, rs, o);

                float alpha = __expf(mi[i] - nm);
                li[i] = li[i] * alpha + rs;
                mi[i] = nm;
                sAl[ty * 4 + i] = alpha;

                char ph8[4], pl8[4];
#pragma unroll
                for (int j = 0; j < 4; j++) {
                    float tt = p[j] * 16256.f;
                    float hv = rintf(tt * (1.f / 128.f));
                    float lv = rintf(tt - 128.f * hv);
                    ph8[j] = (char)(int)hv;
                    pl8[j] = (char)(int)lv;
                }
                uint32_t poff = (uint32_t)((ty * 4 + i) * 80 + tx * 4);
                *(uint32_t*)(dsmem + B_P + poff)        = *(uint32_t*)ph8;
                *(uint32_t*)(dsmem + B_P + 5120 + poff) = *(uint32_t*)pl8;
            }
        }
        __syncthreads();           // P + sAl visible

        // V arrival (per-thread wait; V(t) older than K(t+1) in group order)
        if (t + 1 < nTiles) { CP_WAIT(1); } else { CP_WAIT(0); }

        // ---- O = O*alpha + P V (two-level int8; halves, VALIDATED mapping) ----
        {
            const int er = lane >> 2, ec2 = (lane & 3) * 2;
            const float a0 = sAl[wq * 16 + er];
            const float a1 = sAl[wq * 16 + er + 8];
#pragma unroll
            for (int j = 0; j < 8; j++) {
                oacc[j][0] *= a0; oacc[j][1] *= a0;
                oacc[j][2] *= a1; oacc[j][3] *= a1;
            }
            const uint32_t uPh = sb + B_P;
            const uint32_t uPl = uPh + 5120;
            const uint32_t uVh = sb + B_V;
            const uint32_t uVl = uVh + 10240;
            const float* sVd = (const float*)(dsmem + B_SV);
            const float inv16256 = 1.f / 16256.f;
#pragma unroll
            for (int half = 0; half < 2; half++) {
                int phh[4][4], pxx[4][4];
#pragma unroll
                for (int jj = 0; jj < 4; jj++)
#pragma unroll
                    for (int e = 0; e < 4; e++) { phh[jj][e] = 0; pxx[jj][e] = 0; }
#pragma unroll
                for (int ks = 0; ks < 2; ks++) {
                    const int kk = ks * 16;
                    uint32_t ph[4], pl[4];
                    uint32_t poff = (uint32_t)((a_row * LP8 + kk + a_col) * 2);
                    ldsm4(ph, uPh + poff);
                    ldsm4(pl, uPl + poff);
#pragma unroll
                    for (int nb2 = 0; nb2 < 2; nb2++) {
                        const int nb = half * 2 + nb2;
                        uint32_t voff = (uint32_t)(((bv_row + nb * 16) * LP8 + kk + b_col) * 2);
                        uint32_t vh[4], vl[4];
                        ldsm4(vh, uVh + voff);
                        ldsm4(vl, uVl + voff);
                        mma_s8(phh[nb2 * 2 + 0], ph, vh + 0);
                        mma_s8(phh[nb2 * 2 + 1], ph, vh + 2);
                        mma_s8(pxx[nb2 * 2 + 0], ph, vl + 0);
                        mma_s8(pxx[nb2 * 2 + 1], ph, vl + 2);
                        mma_s8(pxx[nb2 * 2 + 0], pl, vh + 0);
                        mma_s8(pxx[nb2 * 2 + 1], pl, vh + 2);
                    }
                }
#pragma unroll
                for (int jj = 0; jj < 4; jj++) {
                    const int j = half * 4 + jj;
                    int col = wk * 64 + j * 8 + ec2;
                    float sv0 = sVd[col] * inv16256;
                    float sv1 = sVd[col + 1] * inv16256;
                    oacc[j][0] += sv0 * (16384.f * (float)phh[jj][0] + 128.f * (float)pxx[jj][0]);
                    oacc[j][1] += sv1 * (16384.f * (float)phh[jj][1] + 128.f * (float)pxx[jj][1]);
                    oacc[j][2] += sv0 * (16384.f * (float)phh[jj][2] + 128.f * (float)pxx[jj][2]);
                    oacc[j][3] += sv1 * (16384.f * (float)phh[jj][3] + 128.f * (float)pxx[jj][3]);
                }
            }
        }
        // start-of-next-tile __syncthreads() orders V/P/Ss/sAl reuse
    }

    __syncthreads();
    sLi[ty * 4 + 0] = (li[0] > 0.f) ? 1.f / li[0] : 0.f;
    sLi[ty * 4 + 1] = (li[1] > 0.f) ? 1.f / li[1] : 0.f;
    sLi[ty * 4 + 2] = (li[2] > 0.f) ? 1.f / li[2] : 0.f;
    sLi[ty * 4 + 3] = (li[3] > 0.f) ? 1.f / li[3] : 0.f;
    __syncthreads();

    {
        const int er = lane >> 2, ec2 = (lane & 3) * 2;
        float inv0 = sLi[wq * 16 + er];
        float inv1 = sLi[wq * 16 + er + 8];
        size_t grow0 = ((size_t)b * SS + q0 + wq * 16 + er) * 2048;
        size_t grow1 = grow0 + (size_t)8 * 2048;
#pragma unroll
        for (int j = 0; j < 8; j++) {
            size_t colg = (size_t)h * 128 + wk * 64 + j * 8 + ec2;
            *(float2*)(outp + grow0 + colg) =
                make_float2(oacc[j][0] * inv0, oacc[j][1] * inv0);
            *(float2*)(outp + grow1 + colg) =
                make_float2(oacc[j][2] * inv1, oacc[j][3] * inv1);
        }
    }
}

// ---------------------------------------------------------------------------
// Launch
// ---------------------------------------------------------------------------
extern "C" void kernel_launch(void* const* d_in, const int* in_sizes, int n_in,
                              void* d_out, int out_size)
{
    const float* x_q    = (const float*)d_in[0];
    const float* x_kv   = (const float*)d_in[1];
    const float* Wq     = (const float*)d_in[2];
    const float* bq     = (const float*)d_in[3];
    const float* Wk     = (const float*)d_in[4];
    const float* bk     = (const float*)d_in[5];
    const float* Wv     = (const float*)d_in[6];
    const float* bv     = (const float*)d_in[7];
    const float* Wo     = (const float*)d_in[8];
    const float* bo     = (const float*)d_in[9];
    const float* angles = (const float*)d_in[10];
    const int*   amask  = (const int*)d_in[11];
    const int*   causal = (const int*)d_in[12];
    const int*   k_rope = (const int*)d_in[13];
    float* out = (float*)d_out;

    float *q, *k, *v, *attn;
    cudaGetSymbolAddress((void**)&q,    g_q);
    cudaGetSymbolAddress((void**)&k,    g_k);
    cudaGetSymbolAddress((void**)&v,    g_v);
    cudaGetSymbolAddress((void**)&attn, g_attn);

    char *xq_h, *xq_l, *xkv_h, *xkv_l, *at_h, *at_l;
    char *wq_h, *wq_l, *wk_h, *wk_l, *wv_h, *wv_l, *wo_h, *wo_l;
    float *sxq, *sxkv, *sat, *swq, *swk, *swv, *swo;
    cudaGetSymbolAddress((void**)&xq_h,  g_xq_h);
    cudaGetSymbolAddress((void**)&xq_l,  g_xq_l);
    cudaGetSymbolAddress((void**)&xkv_h, g_xkv_h);
    cudaGetSymbolAddress((void**)&xkv_l, g_xkv_l);
    cudaGetSymbolAddress((void**)&at_h,  g_at_h);
    cudaGetSymbolAddress((void**)&at_l,  g_at_l);
    cudaGetSymbolAddress((void**)&wq_h,  g_wq_h);
    cudaGetSymbolAddress((void**)&wq_l,  g_wq_l);
    cudaGetSymbolAddress((void**)&wk_h,  g_wk_h);
    cudaGetSymbolAddress((void**)&wk_l,  g_wk_l);
    cudaGetSymbolAddress((void**)&wv_h,  g_wv_h);
    cudaGetSymbolAddress((void**)&wv_l,  g_wv_l);
    cudaGetSymbolAddress((void**)&wo_h,  g_wo_h);
    cudaGetSymbolAddress((void**)&wo_l,  g_wo_l);
    cudaGetSymbolAddress((void**)&sxq,  g_sxq);
    cudaGetSymbolAddress((void**)&sxkv, g_sxkv);
    cudaGetSymbolAddress((void**)&sat,  g_sat);
    cudaGetSymbolAddress((void**)&swq,  g_swq);
    cudaGetSymbolAddress((void**)&swk,  g_swk);
    cudaGetSymbolAddress((void**)&swv,  g_swv);
    cudaGetSymbolAddress((void**)&swo,  g_swo);

    char *q8h, *q8l, *k8h, *k8l, *v8h, *v8l;
    float *sq8, *sk8, *svt;
    cudaGetSymbolAddress((void**)&q8h, g_q8h);
    cudaGetSymbolAddress((void**)&q8l, g_q8l);
    cudaGetSymbolAddress((void**)&k8h, g_k8h);
    cudaGetSymbolAddress((void**)&k8l, g_k8l);
    cudaGetSymbolAddress((void**)&v8h, g_v8h);
    cudaGetSymbolAddress((void**)&v8l, g_v8l);
    cudaGetSymbolAddress((void**)&sq8, g_sq8);
    cudaGetSymbolAddress((void**)&sk8, g_sk8);
    cudaGetSymbolAddress((void**)&svt, g_svt);

    const int M = MM, N = EE, K = EE;

    cudaFuncSetAttribute(gemm_s8_kernel,
                         cudaFuncAttributeMaxDynamicSharedMemorySize, GEMM_SMEM_BYTES);
    cudaFuncSetAttribute(attn_mma_kernel,
                         cudaFuncAttributeMaxDynamicSharedMemorySize, ATTN_SMEM_BYTES);
    dim3 gGrid(N / GBN, M / GBM);   // (16, 64)

    // quantize inputs + weights
    quant_rows_kernel<<<MM, 256>>>(x_q,  xq_h,  xq_l,  sxq);
    quant_rows_kernel<<<MM, 256>>>(x_kv, xkv_h, xkv_l, sxkv);
    quant_rows_kernel<<<EE, 256>>>(Wq, wq_h, wq_l, swq);
    quant_rows_kernel<<<EE, 256>>>(Wk, wk_h, wk_l, swk);
    quant_rows_kernel<<<EE, 256>>>(Wv, wv_h, wv_l, swv);
    quant_rows_kernel<<<EE, 256>>>(Wo, wo_h, wo_l, swo);

    // projections (fp32 out)
    gemm_s8_kernel<<<gGrid, 512, GEMM_SMEM_BYTES>>>(
        xq_h,  xq_l,  wq_h, wq_l, sxq,  swq, bq, q, M, N, K);
    gemm_s8_kernel<<<gGrid, 512, GEMM_SMEM_BYTES>>>(
        xkv_h, xkv_l, wk_h, wk_l, sxkv, swk, bk, k, M, N, K);
    gemm_s8_kernel<<<gGrid, 512, GEMM_SMEM_BYTES>>>(
        xkv_h, xkv_l, wv_h, wv_l, sxkv, swv, bv, v, M, N, K);

    // fused rope + int8 quant, V tile-column quant
    const int rqBlocks = BB * SS * HH / 4;   // 32768
    rope_quant_kernel<<<rqBlocks, 128>>>(q, angles, k_rope, 1, q8h, q8l, sq8);
    rope_quant_kernel<<<rqBlocks, 128>>>(k, angles, k_rope, 0, k8h, k8l, sk8);
    vquant_kernel<<<BB * HH * 32, 128>>>(v, v8h, v8l, svt);

    // attention (int8 MMA path, 2 CTAs/SM, fp32 out)
    dim3 aGrid(BB * HH, SS / ATQ);   // (64, 32)
    attn_mma_kernel<<<aGrid, 256, ATTN_SMEM_BYTES>>>(
        q8h, q8l, k8h, k8l, sq8, sk8, v8h, v8l, svt, amask, causal, attn);

    // re-quantize attention output, final projection
    quant_rows_kernel<<<MM, 256>>>(attn, at_h, at_l, sat);
    gemm_s8_kernel<<<gGrid, 512, GEMM_SMEM_BYTES>>>(
        at_h, at_l, wo_h, wo_l, sat, swo, bo, out, M, N, K);
}